// round 12
// baseline (speedup 1.0000x reference)
#include <cuda_runtime.h>
#include <math.h>

#define BB 64
#define TT 512
#define FF 64
#define EE 256
#define HH 512
#define GG 2048   // 4*H
#define OO 128
#define NBLK 128

// ---------------- device scratch (no allocations allowed) ----------------
__device__ float g_xg[(size_t)TT * NBLK * 16 * 64];  // [t][blk][c(16)][b(64)]  256 MB
__device__ float g_Wc[GG * FF];                      // fused W_ih @ W_emb
__device__ float g_biasc[GG];
__device__ float g_h[2][HH * BB];                    // [buf][k][b]  k-major
__device__ float g_hsum[BB * HH];                    // [b][k]
struct BarCnt { unsigned v; unsigned pad[63]; };     // 256B apart -> distinct L2 sets
__device__ BarCnt g_cnt[16];

// ---------------- f32x2 helpers ----------------
__device__ __forceinline__ void ffma2(unsigned long long& d, unsigned long long a,
                                      unsigned long long b) {
    asm("fma.rn.f32x2 %0, %1, %2, %3;" : "=l"(d) : "l"(a), "l"(b), "l"(d));
}
__device__ __forceinline__ unsigned long long dup2(float x) {
    unsigned long long r; unsigned u = __float_as_uint(x);
    asm("mov.b64 %0, {%1, %1};" : "=l"(r) : "r"(u));
    return r;
}
__device__ __forceinline__ float lo32(unsigned long long v) { return __uint_as_float((unsigned)v); }
__device__ __forceinline__ float hi32(unsigned long long v) { return __uint_as_float((unsigned)(v >> 32)); }

__device__ __forceinline__ void cpasync16(float* dst_smem, const float* src) {
    unsigned saddr = (unsigned)__cvta_generic_to_shared(dst_smem);
    asm volatile("cp.async.cg.shared.global [%0], [%1], 16;" :: "r"(saddr), "l"(src));
}
#define CP_COMMIT() asm volatile("cp.async.commit_group;")
#define CP_WAITN(n) asm volatile("cp.async.wait_group %0;" :: "n"(n))

__device__ __forceinline__ float ftanh(float x) {
    x = fminf(fmaxf(x, -15.f), 15.f);
    float e = __expf(2.f * x);
    return (e - 1.f) / (e + 1.f);
}
__device__ __forceinline__ float fsig(float x) { return 1.f / (1.f + __expf(-x)); }

// ---------------- 1. fuse weights: Wc = W_ih @ W_emb ----------------
__global__ void fuse_weights_kernel(const float* __restrict__ Wih,
                                    const float* __restrict__ Wemb,
                                    const float* __restrict__ bemb,
                                    const float* __restrict__ bih,
                                    const float* __restrict__ bhh) {
    int g = blockIdx.x;
    int f = threadIdx.x;
    __shared__ float s[EE];
    for (int e = f; e < EE; e += 64) s[e] = Wih[g * EE + e];
    __syncthreads();
    float acc = 0.f;
#pragma unroll 8
    for (int e = 0; e < EE; e++) acc += s[e] * Wemb[e * FF + f];
    g_Wc[g * FF + f] = acc;
    if (f == 0) {
        float bb = 0.f;
        for (int e = 0; e < EE; e++) bb += s[e] * bemb[e];
        g_biasc[g] = bb + bih[g] + bhh[g];
    }
}

// ---------------- 2. xg = x @ Wc^T + biasc, permuted out [t][blk][c][b] --------
__global__ __launch_bounds__(256) void xg_kernel(const float* __restrict__ x) {
    __shared__ __align__(16) float xs[FF][68];   // [k][b]
    __shared__ __align__(16) float ws[FF][68];   // [k][col]
    int tb = blockIdx.x;                  // token index t
    int cbase = blockIdx.y * 64;
    int tid = threadIdx.x;
#pragma unroll
    for (int i = 0; i < 16; i++) {
        int idx = i * 256 + tid;
        int r = idx >> 6, k = idx & 63;
        xs[k][r] = x[((size_t)r * TT + tb) * FF + k];           // b = r
        ws[k][r] = g_Wc[(size_t)(cbase + r) * FF + k];
    }
    __syncthreads();
    int rg = tid & 15, cg = tid >> 4;
    int r0 = rg * 4, c0 = cg * 4;
    unsigned long long acc[4][2] = {};
#pragma unroll 4
    for (int k = 0; k < FF; k++) {
        float4 hv = *(const float4*)&xs[k][r0];
        ulonglong2 wv = *(const ulonglong2*)&ws[k][c0];
        unsigned long long h0 = dup2(hv.x), h1 = dup2(hv.y), h2 = dup2(hv.z), h3 = dup2(hv.w);
        ffma2(acc[0][0], h0, wv.x); ffma2(acc[0][1], h0, wv.y);
        ffma2(acc[1][0], h1, wv.x); ffma2(acc[1][1], h1, wv.y);
        ffma2(acc[2][0], h2, wv.x); ffma2(acc[2][1], h2, wv.y);
        ffma2(acc[3][0], h3, wv.x); ffma2(acc[3][1], h3, wv.y);
    }
#pragma unroll
    for (int j = 0; j < 4; j++) {
        int g = cbase + c0 + j;
        float bias = g_biasc[g];
        int blk = (g & 511) >> 2;
        int cc = ((g >> 9) << 2) + (g & 3);
        float4 v;
        v.x = ((j & 1) ? hi32(acc[0][j >> 1]) : lo32(acc[0][j >> 1])) + bias;
        v.y = ((j & 1) ? hi32(acc[1][j >> 1]) : lo32(acc[1][j >> 1])) + bias;
        v.z = ((j & 1) ? hi32(acc[2][j >> 1]) : lo32(acc[2][j >> 1])) + bias;
        v.w = ((j & 1) ? hi32(acc[3][j >> 1]) : lo32(acc[3][j >> 1])) + bias;
        *(float4*)&g_xg[((((size_t)tb * NBLK + blk) * 16 + cc) << 6) + r0] = v;
    }
}

// ---------------- 3. init ----------------
__global__ void init_state_kernel() {
    int i = blockIdx.x * 256 + threadIdx.x;
    if (i < HH * BB) g_h[0][i] = 0.f;
    if (i < 16) g_cnt[i].v = 0u;
}

// ---------------- 4. persistent LSTM: all 512 steps in one kernel ------------
// 128 blocks x 512 threads (16 warps = 8 k-groups x 2 col-halves).
// smem: W plain [512k][16c] 32KB | h [512k][64b] 128KB | red [8][64 str17][16] 34KB
// Warp (kg,ch) computes its 64-k slice x 8 cols; cp.asyncs only its own 32-k
// half (4 x 2KB pipelined groups), named pair-barrier, then sibling half.
// Grid barrier between steps: R9 distributed-counter parallel-poll.
__global__ __launch_bounds__(512, 1) void lstm_persist(const float* __restrict__ Whh) {
    extern __shared__ __align__(16) float smem[];
    float* ws  = smem;                 // 8192 floats
    float* hs  = smem + 8192;          // 32768 floats
    float* red = smem + 40960;         // 8*64*17 = 8704 floats

    int tid = threadIdx.x;
    int blk = blockIdx.x;
    int j0 = blk * 4;

    int w = tid >> 5, lane = tid & 31;
    int kg = w >> 1;                   // k-group 0..7 (64 k each)
    int ch = w & 1;                    // col half 0/1
    int b0 = (lane & 7) * 8;           // 8 batches
    int c0 = ch * 8 + (lane >> 3) * 2; // 2 gate-cols

    // epilogue mapping (tid<256): one thread per (b, jj)
    int eb = tid & 63, ejj = tid >> 6;

    // load W_hh slice (16 cols x 512 k), plain floats [k][16]
    for (int idx = tid; idx < 16 * 512; idx += 512) {
        int k = idx >> 4, c = idx & 15;
        int g = ((c >> 2) << 9) + j0 + (c & 3);   // gate*512 + j
        ws[k * 16 + c] = Whh[(size_t)g * HH + k];
    }
    __syncthreads();

    float c_reg = 0.f, hsum_reg = 0.f;

    const float* hsl = hs + kg * 4096;
    const float* wsl = ws + kg * 64 * 16;
    int ownk = ch * 32;                // own half base (k units within slice)
    int sibk = 32 - ownk;

#define KLOOP(K0, KN, UN)                                                      \
    _Pragma(UN)                                                                \
    for (int kk = (K0); kk < (K0) + (KN); kk++) {                              \
        float2 wv = *(const float2*)&wsl[kk * 16 + c0];                        \
        unsigned long long w0 = dup2(wv.x), w1 = dup2(wv.y);                   \
        ulonglong2 hA = *(const ulonglong2*)&hsl[kk * 64 + b0];                \
        ulonglong2 hB = *(const ulonglong2*)&hsl[kk * 64 + b0 + 4];            \
        ffma2(acc[0][0], hA.x, w0); ffma2(acc[0][1], hA.x, w1);                \
        ffma2(acc[1][0], hA.y, w0); ffma2(acc[1][1], hA.y, w1);                \
        ffma2(acc[2][0], hB.x, w0); ffma2(acc[2][1], hB.x, w1);                \
        ffma2(acc[3][0], hB.y, w0); ffma2(acc[3][1], hB.y, w1);                \
    }

    for (int t = 0; t < TT; t++) {
        const float* hcur = g_h[t & 1];
        float* hnxt = g_h[(t + 1) & 1];

        // prefetch this step's xg gate values (consumed at epilogue)
        float xv0 = 0.f, xv1 = 0.f, xv2 = 0.f, xv3 = 0.f;
        if (tid < 256) {
            const float* xp = g_xg + (size_t)t * (NBLK * 1024) + ((size_t)blk * 16 + ejj) * 64 + eb;
            xv0 = __ldcg(xp); xv1 = __ldcg(xp + 256);
            xv2 = __ldcg(xp + 512); xv3 = __ldcg(xp + 768);
        }

        // issue own 32-k half as 4 pipelined 2KB groups
        {
            int base = kg * 4096 + ch * 2048;
#pragma unroll
            for (int i = 0; i < 4; i++) {
#pragma unroll
                for (int q = 0; q < 4; q++) {
                    int off = base + i * 512 + (q * 32 + lane) * 4;
                    cpasync16(hs + off, hcur + off);
                }
                CP_COMMIT();
            }
        }

        unsigned long long acc[4][2] = {};   // [batch-pair][col]

        // own half: pipelined 8-k chunks
        CP_WAITN(3); __syncwarp(); KLOOP(ownk,      8, "unroll")
        CP_WAITN(2); __syncwarp(); KLOOP(ownk + 8,  8, "unroll")
        CP_WAITN(1); __syncwarp(); KLOOP(ownk + 16, 8, "unroll")
        CP_WAITN(0); __syncwarp(); KLOOP(ownk + 24, 8, "unroll")

        // pair barrier: sibling's half now resident
        asm volatile("bar.sync %0, 64;" :: "r"(1 + kg) : "memory");

        // sibling half: straight from smem
        KLOOP(sibk, 32, "unroll 8")

        // partials -> red[kg][b][c] (stride 17 to avoid bank conflicts)
#pragma unroll
        for (int p = 0; p < 4; p++) {
            float* r0p = red + kg * 1088 + (b0 + 2 * p) * 17 + c0;
            float* r1p = r0p + 17;
#pragma unroll
            for (int j = 0; j < 2; j++) {
                r0p[j] = lo32(acc[p][j]);
                r1p[j] = hi32(acc[p][j]);
            }
        }
        __syncthreads();

        // epilogue (tid<256): reduce 8 k-groups, activations, state update
        if (tid < 256) {
            float gs0 = 0.f, gs1 = 0.f, gs2 = 0.f, gs3 = 0.f;
#pragma unroll
            for (int q = 0; q < 8; q++) {
                const float* rr = red + q * 1088 + eb * 17 + ejj;
                gs0 += rr[0]; gs1 += rr[4]; gs2 += rr[8]; gs3 += rr[12];
            }
            float iv = fsig(gs0 + xv0);
            float fv = fsig(gs1 + xv1);
            float gv = ftanh(gs2 + xv2);
            float ov = fsig(gs3 + xv3);
            c_reg = fv * c_reg + iv * gv;
            float hn = ov * ftanh(c_reg);
            hnxt[(j0 + ejj) * 64 + eb] = hn;   // [k][b] coalesced
            hsum_reg += hn;
        }

        // grid barrier (R9): fence + distributed counters + parallel poll
        if (t < TT - 1) {
            __threadfence();
            __syncthreads();
            if (tid == 0) atomicAdd(&g_cnt[blk & 15].v, 1u);
            if (tid < 16) {
                unsigned want = 8u * (unsigned)(t + 1);
                while (*(volatile unsigned*)&g_cnt[tid].v < want) { }
            }
            __syncthreads();
            __threadfence();
        }
    }
#undef KLOOP
    if (tid < 256) g_hsum[eb * HH + j0 + ejj] = hsum_reg;
}

// ---------------- 5. pooled = hsum/512 ; out = pooled @ W_fc^T + b_fc --------
__global__ void pool_fc_kernel(const float* __restrict__ Wfc,
                               const float* __restrict__ bfc,
                               float* __restrict__ out) {
    int b = blockIdx.x;
    __shared__ float sh[HH];
    int tid = threadIdx.x;
    for (int k = tid; k < HH; k += 256) sh[k] = g_hsum[b * HH + k];
    __syncthreads();
    int warp = tid >> 5, lane = tid & 31;
    for (int o = warp; o < OO; o += 8) {
        float a = 0.f;
        for (int k = lane; k < HH; k += 32) a += sh[k] * Wfc[o * HH + k];
#pragma unroll
        for (int s = 16; s; s >>= 1) a += __shfl_xor_sync(0xffffffffu, a, s);
        if (lane == 0) out[b * OO + o] = a * (1.f / 512.f) + bfc[o];
    }
}

extern "C" void kernel_launch(void* const* d_in, const int* in_sizes, int n_in,
                              void* d_out, int out_size) {
    const float* x    = (const float*)d_in[0];
    const float* Wemb = (const float*)d_in[1];
    const float* bemb = (const float*)d_in[2];
    const float* Wih  = (const float*)d_in[3];
    const float* Whh  = (const float*)d_in[4];
    const float* bih  = (const float*)d_in[5];
    const float* bhh  = (const float*)d_in[6];
    const float* Wfc  = (const float*)d_in[7];
    const float* bfc  = (const float*)d_in[8];
    float* out = (float*)d_out;

    static bool attr_set = false;
    if (!attr_set) {
        cudaFuncSetAttribute(lstm_persist, cudaFuncAttributeMaxDynamicSharedMemorySize, 198656);
        attr_set = true;
    }

    fuse_weights_kernel<<<GG, 64>>>(Wih, Wemb, bemb, bih, bhh);

    dim3 xgrid(TT, GG / 64);
    xg_kernel<<<xgrid, 256>>>(x);

    init_state_kernel<<<(HH * BB + 255) / 256, 256>>>();

    lstm_persist<<<NBLK, 512, 198656>>>(Whh);

    pool_fc_kernel<<<BB, 256>>>(Wfc, bfc, out);
}

// round 14
// speedup vs baseline: 1.8360x; 1.8360x over previous
#include <cuda_runtime.h>
#include <cuda_bf16.h>
#include <math.h>

#define BB 64
#define TT 512
#define FF 64
#define EE 256
#define HH 512
#define GG 2048   // 4*H
#define OO 128
#define NBLK 128

// ---------------- device scratch ----------------
__device__ float g_xg[(size_t)TT * NBLK * 16 * 64];  // [t][blk][c(16)][b(64)]
__device__ float g_Wc[GG * FF];
__device__ float g_biasc[GG];
__device__ unsigned short g_h16[2][2][64 * 512];     // [buf][hi|lo][b*512+k] bf16
__device__ float g_hsum[BB * HH];
struct BarCnt { unsigned v; unsigned pad[63]; };
__device__ BarCnt g_cnt[16];

// smem byte offsets (dynamic smem)
#define S_WHI 0u
#define S_WLO 16640u          // 16*1040
#define S_AHI 33280u
#define S_ALO 99840u          // +64*1040
#define S_RED 166400u         // float[64][20]
#define S_TOT 171520u

// ---------------- helpers ----------------
__device__ __forceinline__ void ffma2(unsigned long long& d, unsigned long long a,
                                      unsigned long long b) {
    asm("fma.rn.f32x2 %0, %1, %2, %3;" : "=l"(d) : "l"(a), "l"(b), "l"(d));
}
__device__ __forceinline__ unsigned long long dup2(float x) {
    unsigned long long r; unsigned u = __float_as_uint(x);
    asm("mov.b64 %0, {%1, %1};" : "=l"(r) : "r"(u));
    return r;
}
__device__ __forceinline__ float lo32(unsigned long long v) { return __uint_as_float((unsigned)v); }
__device__ __forceinline__ float hi32(unsigned long long v) { return __uint_as_float((unsigned)(v >> 32)); }

__device__ __forceinline__ unsigned smem_u32(const void* p) {
    unsigned a;
    asm("{ .reg .u64 t; cvta.to.shared.u64 t, %1; cvt.u32.u64 %0, t; }" : "=r"(a) : "l"(p));
    return a;
}
__device__ __forceinline__ void cpasync16s(unsigned dst, const void* src) {
    asm volatile("cp.async.cg.shared.global [%0], [%1], 16;" :: "r"(dst), "l"(src));
}
#define CP_COMMIT() asm volatile("cp.async.commit_group;")
#define CP_WAITN(n) asm volatile("cp.async.wait_group %0;" :: "n"(n))

__device__ __forceinline__ void ldsm_x4(unsigned& r0, unsigned& r1, unsigned& r2,
                                        unsigned& r3, unsigned addr) {
    asm volatile("ldmatrix.sync.aligned.m8n8.x4.shared.b16 {%0,%1,%2,%3}, [%4];"
                 : "=r"(r0), "=r"(r1), "=r"(r2), "=r"(r3) : "r"(addr));
}
__device__ __forceinline__ void ldsm_x2(unsigned& r0, unsigned& r1, unsigned addr) {
    asm volatile("ldmatrix.sync.aligned.m8n8.x2.shared.b16 {%0,%1}, [%2];"
                 : "=r"(r0), "=r"(r1) : "r"(addr));
}
__device__ __forceinline__ void mma16816(float d[4], unsigned a0, unsigned a1,
                                         unsigned a2, unsigned a3,
                                         unsigned b0, unsigned b1) {
    asm volatile("mma.sync.aligned.m16n8k16.row.col.f32.bf16.bf16.f32 "
                 "{%0,%1,%2,%3}, {%4,%5,%6,%7}, {%8,%9}, {%0,%1,%2,%3};"
                 : "+f"(d[0]), "+f"(d[1]), "+f"(d[2]), "+f"(d[3])
                 : "r"(a0), "r"(a1), "r"(a2), "r"(a3), "r"(b0), "r"(b1));
}

__device__ __forceinline__ float ftanh(float x) {
    x = fminf(fmaxf(x, -15.f), 15.f);
    float e = __expf(2.f * x);
    return (e - 1.f) / (e + 1.f);
}
__device__ __forceinline__ float fsig(float x) { return 1.f / (1.f + __expf(-x)); }

// ---------------- 1. fuse weights: Wc = W_ih @ W_emb ----------------
__global__ void fuse_weights_kernel(const float* __restrict__ Wih,
                                    const float* __restrict__ Wemb,
                                    const float* __restrict__ bemb,
                                    const float* __restrict__ bih,
                                    const float* __restrict__ bhh) {
    int g = blockIdx.x, f = threadIdx.x;
    __shared__ float s[EE];
    for (int e = f; e < EE; e += 64) s[e] = Wih[g * EE + e];
    __syncthreads();
    float acc = 0.f;
#pragma unroll 8
    for (int e = 0; e < EE; e++) acc += s[e] * Wemb[e * FF + f];
    g_Wc[g * FF + f] = acc;
    if (f == 0) {
        float bb = 0.f;
        for (int e = 0; e < EE; e++) bb += s[e] * bemb[e];
        g_biasc[g] = bb + bih[g] + bhh[g];
    }
}

// ---------------- 2. xg = x @ Wc^T + biasc, out [t][blk][c][b] (R9 layout) ----
__global__ __launch_bounds__(256) void xg_kernel(const float* __restrict__ x) {
    __shared__ __align__(16) float xs[FF][68];
    __shared__ __align__(16) float ws[FF][68];
    int tb = blockIdx.x, cbase = blockIdx.y * 64, tid = threadIdx.x;
#pragma unroll
    for (int i = 0; i < 16; i++) {
        int idx = i * 256 + tid;
        int r = idx >> 6, k = idx & 63;
        xs[k][r] = x[((size_t)r * TT + tb) * FF + k];
        ws[k][r] = g_Wc[(size_t)(cbase + r) * FF + k];
    }
    __syncthreads();
    int rg = tid & 15, cg = tid >> 4;
    int r0 = rg * 4, c0 = cg * 4;
    unsigned long long acc[4][2] = {};
#pragma unroll 4
    for (int k = 0; k < FF; k++) {
        float4 hv = *(const float4*)&xs[k][r0];
        ulonglong2 wv = *(const ulonglong2*)&ws[k][c0];
        unsigned long long h0 = dup2(hv.x), h1 = dup2(hv.y), h2 = dup2(hv.z), h3 = dup2(hv.w);
        ffma2(acc[0][0], h0, wv.x); ffma2(acc[0][1], h0, wv.y);
        ffma2(acc[1][0], h1, wv.x); ffma2(acc[1][1], h1, wv.y);
        ffma2(acc[2][0], h2, wv.x); ffma2(acc[2][1], h2, wv.y);
        ffma2(acc[3][0], h3, wv.x); ffma2(acc[3][1], h3, wv.y);
    }
#pragma unroll
    for (int j = 0; j < 4; j++) {
        int g = cbase + c0 + j;
        float bias = g_biasc[g];
        int blk = (g & 511) >> 2;
        int cc = ((g >> 9) << 2) + (g & 3);
        float4 v;
        v.x = ((j & 1) ? hi32(acc[0][j >> 1]) : lo32(acc[0][j >> 1])) + bias;
        v.y = ((j & 1) ? hi32(acc[1][j >> 1]) : lo32(acc[1][j >> 1])) + bias;
        v.z = ((j & 1) ? hi32(acc[2][j >> 1]) : lo32(acc[2][j >> 1])) + bias;
        v.w = ((j & 1) ? hi32(acc[3][j >> 1]) : lo32(acc[3][j >> 1])) + bias;
        *(float4*)&g_xg[((((size_t)tb * NBLK + blk) * 16 + cc) << 6) + r0] = v;
    }
}

// ---------------- 3. init ----------------
__global__ void init_state_kernel() {
    int i = blockIdx.x * 256 + threadIdx.x;
    if (i < 8192) ((uint4*)g_h16[0])[i] = make_uint4(0, 0, 0, 0);  // zero buf0 hi+lo
    if (i < 16) g_cnt[i].v = 0u;
}

// ---------------- 4. persistent LSTM via mma.sync bf16 3-term split ----------
// 128 blocks x 256 threads (8 warps). Block owns 4 hidden units (16 gate-cols).
// Warp w: mt=w>>1 (16 batches), nt=w&1 (8 cols). Pair (2mt,2mt+1) loads its own
// 16 A rows (bf16 hi+lo) via 4 pipelined cp.async k-chunks + named pair barrier.
__global__ __launch_bounds__(256, 1) void lstm_mma(const float* __restrict__ Whh) {
    extern __shared__ __align__(16) unsigned char smem[];
    unsigned sb = smem_u32(smem);
    float* red = (float*)(smem + S_RED);

    int tid = threadIdx.x, wid = tid >> 5, lane = tid & 31;
    int blk = blockIdx.x, j0 = blk * 4;
    int mt = wid >> 1, nt = wid & 1;
    int rbase = wid * 8;                      // this warp's A-load rows

    // one-time W conversion: n = gate*4+jj rows, K-major, bf16 hi/lo, stride 1040B
    for (int idx = tid; idx < 16 * 512; idx += 256) {
        int k = idx & 511, n = idx >> 9;
        float w = Whh[(size_t)((n >> 2) * 512 + j0 + (n & 3)) * 512 + k];
        __nv_bfloat16 hb = __float2bfloat16(w);
        __nv_bfloat16 lb = __float2bfloat16(w - __bfloat162float(hb));
        *(unsigned short*)(smem + S_WHI + n * 1040 + k * 2) = *(unsigned short*)&hb;
        *(unsigned short*)(smem + S_WLO + n * 1040 + k * 2) = *(unsigned short*)&lb;
    }
    __syncthreads();

    // lane-fixed ldmatrix bases
    int q = lane >> 3, r8 = lane & 7;
    unsigned aBase = sb + S_AHI + (unsigned)((mt * 16 + (q & 1) * 8 + r8) * 1040
                                             + ((q >> 1) * 8) * 2);
    unsigned bBase = sb + S_WHI + (unsigned)((nt * 8 + r8) * 1040
                                             + (((lane >> 3) & 1) * 8) * 2);
    // epilogue mapping
    int eb = tid & 63, ejj = tid >> 6;

    float c_reg = 0.f, hsum_reg = 0.f;

    for (int t = 0; t < TT; t++) {
        // xg prefetch
        const float* xp = g_xg + (size_t)t * (NBLK * 1024) + ((size_t)blk * 16 + ejj) * 64 + eb;
        float xv0 = __ldcg(xp), xv1 = __ldcg(xp + 256), xv2 = __ldcg(xp + 512), xv3 = __ldcg(xp + 768);

        // issue own 8 A rows (hi+lo) as 4 k-chunk groups (2KB each)
        const unsigned short* himg = g_h16[t & 1][0];
#pragma unroll
        for (int g = 0; g < 4; g++) {
#pragma unroll
            for (int i = 0; i < 8; i++) {
                int e = i * 32 + lane;
                int prec = e >> 7, e2 = e & 127;
                int row = rbase + (e2 >> 4), kseg = g * 16 + (e2 & 15);
                cpasync16s(sb + S_AHI + prec * 66560u + row * 1040u + kseg * 16u,
                           himg + prec * 32768 + row * 512 + kseg * 8);
            }
            CP_COMMIT();
        }

        float d[4] = {0.f, 0.f, 0.f, 0.f};

#define CHUNK(KC, WN)                                                          \
        CP_WAITN(WN);                                                          \
        asm volatile("bar.sync %0, 64;" :: "r"(1 + mt) : "memory");            \
        {                                                                      \
            _Pragma("unroll")                                                  \
            for (int s = 0; s < 8; s++) {                                      \
                unsigned koff = (unsigned)(((KC) * 128 + s * 16) * 2);         \
                unsigned a0, a1, a2, a3, l0, l1, l2, l3, b0, b1, c0, c1;       \
                ldsm_x4(a0, a1, a2, a3, aBase + koff);                         \
                ldsm_x4(l0, l1, l2, l3, aBase + 66560u + koff);                \
                ldsm_x2(b0, b1, bBase + koff);                                 \
                ldsm_x2(c0, c1, bBase + 16640u + koff);                        \
                mma16816(d, a0, a1, a2, a3, b0, b1);                           \
                mma16816(d, l0, l1, l2, l3, b0, b1);                           \
                mma16816(d, a0, a1, a2, a3, c0, c1);                           \
            }                                                                  \
        }
        CHUNK(0, 3)
        CHUNK(1, 2)
        CHUNK(2, 1)
        CHUNK(3, 0)
#undef CHUNK

        // D frags -> red[b][c] (stride 20 floats)
        {
            int rr = lane >> 2, cc = (lane & 3) * 2;
            float2* p0 = (float2*)&red[(mt * 16 + rr) * 20 + nt * 8 + cc];
            float2* p1 = (float2*)&red[(mt * 16 + 8 + rr) * 20 + nt * 8 + cc];
            *p0 = make_float2(d[0], d[1]);
            *p1 = make_float2(d[2], d[3]);
        }
        __syncthreads();

        // epilogue: one thread per (b, jj)
        {
            const float* rr = &red[eb * 20 + ejj];
            float iv = fsig(rr[0] + xv0);
            float fv = fsig(rr[4] + xv1);
            float gv = ftanh(rr[8] + xv2);
            float ov = fsig(rr[12] + xv3);
            c_reg = fv * c_reg + iv * gv;
            float hn = ov * ftanh(c_reg);
            hsum_reg += hn;
            __nv_bfloat16 hb = __float2bfloat16(hn);
            __nv_bfloat16 lb = __float2bfloat16(hn - __bfloat162float(hb));
            int nb = (t + 1) & 1;
            g_h16[nb][0][eb * 512 + j0 + ejj] = *(unsigned short*)&hb;
            g_h16[nb][1][eb * 512 + j0 + ejj] = *(unsigned short*)&lb;
        }

        // grid barrier (R9 verbatim)
        if (t < TT - 1) {
            __threadfence();
            __syncthreads();
            if (tid == 0) atomicAdd(&g_cnt[blk & 15].v, 1u);
            if (tid < 16) {
                unsigned want = 8u * (unsigned)(t + 1);
                while (*(volatile unsigned*)&g_cnt[tid].v < want) { }
            }
            __syncthreads();
            __threadfence();
        }
    }
    g_hsum[eb * HH + j0 + ejj] = hsum_reg;
}

// ---------------- 5. pool + FC ----------------
__global__ void pool_fc_kernel(const float* __restrict__ Wfc,
                               const float* __restrict__ bfc,
                               float* __restrict__ out) {
    int b = blockIdx.x;
    __shared__ float sh[HH];
    int tid = threadIdx.x;
    for (int k = tid; k < HH; k += 256) sh[k] = g_hsum[b * HH + k];
    __syncthreads();
    int warp = tid >> 5, lane = tid & 31;
    for (int o = warp; o < OO; o += 8) {
        float a = 0.f;
        for (int k = lane; k < HH; k += 32) a += sh[k] * Wfc[o * HH + k];
#pragma unroll
        for (int s = 16; s; s >>= 1) a += __shfl_xor_sync(0xffffffffu, a, s);
        if (lane == 0) out[b * OO + o] = a * (1.f / 512.f) + bfc[o];
    }
}

extern "C" void kernel_launch(void* const* d_in, const int* in_sizes, int n_in,
                              void* d_out, int out_size) {
    const float* x    = (const float*)d_in[0];
    const float* Wemb = (const float*)d_in[1];
    const float* bemb = (const float*)d_in[2];
    const float* Wih  = (const float*)d_in[3];
    const float* Whh  = (const float*)d_in[4];
    const float* bih  = (const float*)d_in[5];
    const float* bhh  = (const float*)d_in[6];
    const float* Wfc  = (const float*)d_in[7];
    const float* bfc  = (const float*)d_in[8];
    float* out = (float*)d_out;

    static bool attr_set = false;
    if (!attr_set) {
        cudaFuncSetAttribute(lstm_mma, cudaFuncAttributeMaxDynamicSharedMemorySize, S_TOT);
        attr_set = true;
    }

    fuse_weights_kernel<<<GG, 64>>>(Wih, Wemb, bemb, bih, bhh);

    dim3 xgrid(TT, GG / 64);
    xg_kernel<<<xgrid, 256>>>(x);

    init_state_kernel<<<32, 256>>>();

    lstm_mma<<<NBLK, 256, S_TOT>>>(Whh);

    pool_fc_kernel<<<BB, 256>>>(Wfc, bfc, out);
}